// round 17
// baseline (speedup 1.0000x reference)
#include <cuda_runtime.h>
#include <cuda_bf16.h>

// relu(segment_sum(x @ W^T + b))  ==  relu(segment_sum(x) @ W^T + count * b)
// N=500000, H=256, B=1024, seg_ids sorted ascending.
//
// TWO kernels:
//  1. segsum: proven 77.2us @ 85% DRAM (roofline, untouched). First 64
//     blocks also write the k-major W copy W4T[k4][j].
//  2. finish: m=8 broadcast-ratio GEMM with 4-way k-split.
//     Evidence R13 vs R16: occupancy is NOT the limiter; the L1 wavefront
//     budget is. wf_total = 524K*(4/m+1): m=2 (R13/R16) -> 1.57M wf =
//     ~11us L1 floor; m=8 -> 786K wf = ~5.6us. Split-k4 keeps 512 blocks
//     resident (m=8 alone would be 128 blocks = R11's latency trap).
//     Partials atomicAdd into preact; last of 32 siblings per seg-tile
//     does bias+count+relu+store and zeros all scratch (no relu kernel).

#define H 256
#define HV 64                  // H/4
#define B 1024
#define TARGET_GRID 1184       // segsum: 148 SMs * 8 blocks ceiling
#define RPI 32                 // segsum rows per iteration
#define FJT 8                  // finish: j tiles (32 j each)
#define FST 16                 // finish: seg tiles (64 segs each)
#define FKH 4                  // finish: k splits (64 k each)

__device__ float g_pooled[B * H];     // [g][k] segment sums (zero-init)
__device__ float g_count[B];          // nodes per segment   (zero-init)
__device__ float g_preact[B * H];     // [g][j] GEMM partials (zero-init;
                                      //   re-zeroed by finish each launch)
__device__ float g_W4T[H * H];        // [k4][j] k-major W (overwritten/launch)
__device__ unsigned int g_done[FST];  // per-seg-tile arrival counters

// ---------------------------------------------------------------------------
// Kernel 1: segment-sum of x (row-major pooled).  At HBM roofline.
// ---------------------------------------------------------------------------
__device__ __forceinline__ void flush_acc(float4& acc, int cur, int c) {
    float* dst = &g_pooled[cur * H + c * 4];
    atomicAdd(dst + 0, acc.x);
    atomicAdd(dst + 1, acc.y);
    atomicAdd(dst + 2, acc.z);
    atomicAdd(dst + 3, acc.w);
    acc = make_float4(0.f, 0.f, 0.f, 0.f);
}

__global__ void __launch_bounds__(H) segsum_kernel(
    const float* __restrict__ x, const int* __restrict__ seg,
    const float* __restrict__ W, int N, int rows_per_block)
{
    // preamble: blocks 0..63 write W4T[k4=blockIdx][j=tid] (one float4 each)
    if (blockIdx.x < 64) {
        reinterpret_cast<float4*>(g_W4T)[blockIdx.x * 256 + threadIdx.x] =
            __ldg(&reinterpret_cast<const float4*>(W)[threadIdx.x * HV + blockIdx.x]);
    }

    int r0 = blockIdx.x * rows_per_block;
    int r1 = min(r0 + rows_per_block, N);
    if (r0 >= r1) return;

    const int tid    = threadIdx.x;
    const int c      = tid & 63;
    const int rowoff = tid >> 6;
    const float4* __restrict__ x4 = reinterpret_cast<const float4*>(x);

    float4 acc = make_float4(0.f, 0.f, 0.f, 0.f);
    int cur       = __ldg(&seg[r0]);
    int run_start = r0;

    int r = r0;
    for (; r + RPI <= r1; r += RPI) {
        size_t base = (size_t)(r + rowoff) * HV + c;
        float4 v0 = __ldg(&x4[base + 0 * 4 * HV]);
        float4 v1 = __ldg(&x4[base + 1 * 4 * HV]);
        float4 v2 = __ldg(&x4[base + 2 * 4 * HV]);
        float4 v3 = __ldg(&x4[base + 3 * 4 * HV]);
        float4 v4 = __ldg(&x4[base + 4 * 4 * HV]);
        float4 v5 = __ldg(&x4[base + 5 * 4 * HV]);
        float4 v6 = __ldg(&x4[base + 6 * 4 * HV]);
        float4 v7 = __ldg(&x4[base + 7 * 4 * HV]);
        int s_last = __ldg(&seg[r + RPI - 1]);

        if (s_last == cur) {
            acc.x += ((v0.x + v1.x) + (v2.x + v3.x)) + ((v4.x + v5.x) + (v6.x + v7.x));
            acc.y += ((v0.y + v1.y) + (v2.y + v3.y)) + ((v4.y + v5.y) + (v6.y + v7.y));
            acc.z += ((v0.z + v1.z) + (v2.z + v3.z)) + ((v4.z + v5.z) + (v6.z + v7.z));
            acc.w += ((v0.w + v1.w) + (v2.w + v3.w)) + ((v4.w + v5.w) + (v6.w + v7.w));
        } else {
            float4 vv[8] = {v0, v1, v2, v3, v4, v5, v6, v7};
            #pragma unroll
            for (int k = 0; k < RPI; ++k) {
                int rr = r + k;
                int s = __ldg(&seg[rr]);
                if (s != cur) {
                    flush_acc(acc, cur, c);
                    if (tid == 0)
                        atomicAdd(&g_count[cur], (float)(rr - run_start));
                    cur = s; run_start = rr;
                }
                if ((k & 3) == rowoff) {
                    float4 v = vv[k >> 2];
                    acc.x += v.x; acc.y += v.y; acc.z += v.z; acc.w += v.w;
                }
            }
        }
    }
    for (; r < r1; ++r) {
        int s = __ldg(&seg[r]);
        if (s != cur) {
            flush_acc(acc, cur, c);
            if (tid == 0) atomicAdd(&g_count[cur], (float)(r - run_start));
            cur = s; run_start = r;
        }
        if (rowoff == 0) {
            float4 v = __ldg(&x4[(size_t)r * HV + c]);
            acc.x += v.x; acc.y += v.y; acc.z += v.z; acc.w += v.w;
        }
    }
    flush_acc(acc, cur, c);
    if (tid == 0) atomicAdd(&g_count[cur], (float)(r1 - run_start));
}

// ---------------------------------------------------------------------------
// Kernel 2: finish. 512 blocks = 8 jt x 16 st x 4 kh; 256 threads (8 warps).
// Block: 32 j x 64 segs x 64 k. Warp = 32 j (lane) x 8 segs; thread's k
// range = 16 float4. Per k4 per warp: 1 conflict-free LDS.128 (W tile,
// 4 wf) + 8 NAMED uniform pooled LDGs (1 wf each) + 32 FFMA/thread.
// Partials -> atomicAdd preact. Last of 32 siblings per st does
// bias+count+relu+store and zeros preact/pooled/count.
// ---------------------------------------------------------------------------
__global__ void __launch_bounds__(256) finish_kernel(
    const float* __restrict__ bias, float* __restrict__ out)
{
    const int t    = threadIdx.x;
    const int jt   = blockIdx.x & (FJT - 1);
    const int st   = (blockIdx.x >> 3) & (FST - 1);
    const int kh   = blockIdx.x >> 7;        // 0..3
    const int j0   = jt * 32;
    const int g0   = st * 64;
    const int jl   = t & 31;
    const int wp   = t >> 5;                 // 0..7
    const int gw   = g0 + wp * 8;            // warp's first segment
    const int k4_0 = kh * 16;                // this block's k4 range start

    __shared__ __align__(16) float4 sws[16 * 32];   // 8KB W tile
    __shared__ int s_last;

    // ---- stage W tile (coalesced, 2 float4/thread) ----
    {
        const float4* __restrict__ w4t = reinterpret_cast<const float4*>(g_W4T);
        #pragma unroll
        for (int i = 0; i < 2; ++i) {
            int idx = t + i * 256;           // 0..511
            int k4  = idx >> 5;
            int jj  = idx & 31;
            sws[idx] = __ldg(&w4t[(k4_0 + k4) * 256 + j0 + jj]);
        }
    }
    __syncthreads();

    const float4* __restrict__ p4 =
        reinterpret_cast<const float4*>(g_pooled) + (size_t)gw * HV + k4_0;

    float a0 = 0.f, a1 = 0.f, a2 = 0.f, a3 = 0.f;
    float a4 = 0.f, a5 = 0.f, a6 = 0.f, a7 = 0.f;

    for (int k4 = 0; k4 < 16; k4 += 1) {
        float4 w  = sws[k4 * 32 + jl];
        float4 p0 = __ldg(&p4[0 * HV + k4]);
        float4 p1 = __ldg(&p4[1 * HV + k4]);
        float4 p2 = __ldg(&p4[2 * HV + k4]);
        float4 p3 = __ldg(&p4[3 * HV + k4]);
        float4 p4v = __ldg(&p4[4 * HV + k4]);
        float4 p5 = __ldg(&p4[5 * HV + k4]);
        float4 p6 = __ldg(&p4[6 * HV + k4]);
        float4 p7 = __ldg(&p4[7 * HV + k4]);
        a0 += w.x * p0.x + w.y * p0.y + w.z * p0.z + w.w * p0.w;
        a1 += w.x * p1.x + w.y * p1.y + w.z * p1.z + w.w * p1.w;
        a2 += w.x * p2.x + w.y * p2.y + w.z * p2.z + w.w * p2.w;
        a3 += w.x * p3.x + w.y * p3.y + w.z * p3.z + w.w * p3.w;
        a4 += w.x * p4v.x + w.y * p4v.y + w.z * p4v.z + w.w * p4v.w;
        a5 += w.x * p5.x + w.y * p5.y + w.z * p5.z + w.w * p5.w;
        a6 += w.x * p6.x + w.y * p6.y + w.z * p6.z + w.w * p6.w;
        a7 += w.x * p7.x + w.y * p7.y + w.z * p7.z + w.w * p7.w;
    }

    // ---- accumulate partials (coalesced REDs, 8 per thread) ----
    {
        float* pre = g_preact + (size_t)gw * H + j0 + jl;
        atomicAdd(pre + 0 * H, a0);
        atomicAdd(pre + 1 * H, a1);
        atomicAdd(pre + 2 * H, a2);
        atomicAdd(pre + 3 * H, a3);
        atomicAdd(pre + 4 * H, a4);
        atomicAdd(pre + 5 * H, a5);
        atomicAdd(pre + 6 * H, a6);
        atomicAdd(pre + 7 * H, a7);
    }

    // ---- arrival: last of 32 siblings (8 jt x 4 kh) finalizes this st ----
    __syncthreads();
    if (t == 0) {
        __threadfence();                     // publish REDs before counting
        s_last = (atomicAdd(&g_done[st], 1u) == 8 * FKH - 1) ? 1 : 0;
    }
    __syncthreads();
    if (s_last) {
        __threadfence();                     // acquire siblings' REDs
        float4* pre4 = reinterpret_cast<float4*>(g_preact) + (size_t)g0 * HV;
        float4* poo4 = reinterpret_cast<float4*>(g_pooled) + (size_t)g0 * HV;
        float4* out4 = reinterpret_cast<float4*>(out) + (size_t)g0 * HV;
        const float4* b4 = reinterpret_cast<const float4*>(bias);
        const float4 z = make_float4(0.f, 0.f, 0.f, 0.f);

        for (int i = t; i < 64 * HV; i += 256) {     // 16 iters/thread
            int g  = g0 + (i >> 6);
            int c4 = i & 63;
            float4 p  = pre4[i];
            float  cn = g_count[g];
            float4 bb = __ldg(&b4[c4]);
            float4 o;
            o.x = fmaxf(p.x + cn * bb.x, 0.f);
            o.y = fmaxf(p.y + cn * bb.y, 0.f);
            o.z = fmaxf(p.z + cn * bb.z, 0.f);
            o.w = fmaxf(p.w + cn * bb.w, 0.f);
            out4[i] = o;
            pre4[i] = z;
            poo4[i] = z;
        }
        __syncthreads();                     // count reads done before zeroing
        if (t < 64) g_count[g0 + t] = 0.f;
        if (t == 0) g_done[st] = 0u;
    }
}

// ---------------------------------------------------------------------------
// Launch
// ---------------------------------------------------------------------------
extern "C" void kernel_launch(void* const* d_in, const int* in_sizes, int n_in,
                              void* d_out, int out_size)
{
    const float* x   = (const float*)d_in[0];   // [N, 256]
    const int*   seg = (const int*)  d_in[1];   // [N]
    const float* W   = (const float*)d_in[2];   // [256, 256]
    const float* b   = (const float*)d_in[3];   // [256]
    float* out = (float*)d_out;                 // [1024, 256]

    const int N = in_sizes[0] / H;

    int rpb = (N + TARGET_GRID - 1) / TARGET_GRID;
    rpb = ((rpb + RPI - 1) / RPI) * RPI;        // N=500000 -> 448
    int grid = (N + rpb - 1) / rpb;             // -> 1117

    segsum_kernel<<<grid, H>>>(x, seg, W, N, rpb);
    finish_kernel<<<FJT * FST * FKH, 256>>>(b, out);
}